// round 4
// baseline (speedup 1.0000x reference)
#include <cuda_runtime.h>
#include <stdint.h>

// HDCTokenEncoder: out[b,i,d] = item_memory[tok[b,i]][(d - i) mod D] * 0.01f
// (L2 norm of every +/-1 row of length 10000 is exactly 100 in fp32)

#define HDC_D    10000
#define HDC_D4   2500      // D / 4
#define HDC_S    2048
#define NTHREADS 256

__global__ void __launch_bounds__(NTHREADS)
hdc_encode_kernel(const int* __restrict__ tok,
                  const float4* __restrict__ item,   // [V][D4]
                  float4* __restrict__ out)          // [B*S][D4]
{
    __shared__ float4 s[HDC_D4];   // 40 KB: one rotated row

    const int row = blockIdx.x;          // 0 .. B*S-1
    const int i   = row & (HDC_S - 1);   // position within sequence
    const int t   = tok[row];

    const int Dmi = HDC_D - i;           // rotation amount: out[d] = row[(d + Dmi) % D]
    int r4        = Dmi >> 2;            // rotation in float4 units (may be 2500 when i==0)
    const int a   = Dmi & 3;             // residual element shift 0..3
    if (r4 >= HDC_D4) r4 -= HDC_D4;

    const float4* __restrict__ src = item + (size_t)t * HDC_D4;

    // Stage: s[p] = row4[(p + r4) % D4]  -> s (flattened) = row rotated by 4*r4 floats.
    // Global reads are contiguous/coalesced except at the single wrap point.
    for (int p = threadIdx.x; p < HDC_D4; p += NTHREADS) {
        int k = p + r4;
        if (k >= HDC_D4) k -= HDC_D4;
        s[p] = src[k];
    }
    __syncthreads();

    float4* __restrict__ orow = out + (size_t)row * HDC_D4;
    const float sc = 0.01f;

    // out4[q] = s_flat[4q + a .. 4q + a + 3]  (mod D). Four specialized loops so the
    // component selection is compile-time (pure register moves, no local-mem indexing).
    if (a == 0) {
        for (int q = threadIdx.x; q < HDC_D4; q += NTHREADS) {
            float4 A = s[q];
            float4 v; v.x = A.x * sc; v.y = A.y * sc; v.z = A.z * sc; v.w = A.w * sc;
            orow[q] = v;
        }
    } else if (a == 1) {
        for (int q = threadIdx.x; q < HDC_D4; q += NTHREADS) {
            float4 A = s[q];
            int qn = q + 1; if (qn == HDC_D4) qn = 0;
            float4 B = s[qn];
            float4 v; v.x = A.y * sc; v.y = A.z * sc; v.z = A.w * sc; v.w = B.x * sc;
            orow[q] = v;
        }
    } else if (a == 2) {
        for (int q = threadIdx.x; q < HDC_D4; q += NTHREADS) {
            float4 A = s[q];
            int qn = q + 1; if (qn == HDC_D4) qn = 0;
            float4 B = s[qn];
            float4 v; v.x = A.z * sc; v.y = A.w * sc; v.z = B.x * sc; v.w = B.y * sc;
            orow[q] = v;
        }
    } else {
        for (int q = threadIdx.x; q < HDC_D4; q += NTHREADS) {
            float4 A = s[q];
            int qn = q + 1; if (qn == HDC_D4) qn = 0;
            float4 B = s[qn];
            float4 v; v.x = A.w * sc; v.y = B.x * sc; v.z = B.y * sc; v.w = B.z * sc;
            orow[q] = v;
        }
    }
}

extern "C" void kernel_launch(void* const* d_in, const int* in_sizes, int n_in,
                              void* d_out, int out_size)
{
    // Inputs per metadata order: token_ids (int32, B*S=16384), item_memory (f32, V*D).
    // Be robust to ordering: tokens is the smaller buffer.
    const void* p0 = d_in[0];
    const void* p1 = d_in[1];
    const int*    tok;
    const float4* item;
    int n_rows;
    if (in_sizes[0] <= in_sizes[1]) {
        tok    = (const int*)p0;
        item   = (const float4*)p1;
        n_rows = in_sizes[0];
    } else {
        tok    = (const int*)p1;
        item   = (const float4*)p0;
        n_rows = in_sizes[1];
    }

    float4* out = (float4*)d_out;
    hdc_encode_kernel<<<n_rows, NTHREADS>>>(tok, item, out);
}

// round 6
// speedup vs baseline: 1.3858x; 1.3858x over previous
#include <cuda_runtime.h>
#include <stdint.h>

// HDCTokenEncoder: out[b,i,d] = item_memory[tok[b,i]][(d - i) mod D] * 0.01f
// (L2 norm of every +/-1 row of length 10000 is exactly 100, exact in fp32,
//  so normalization == multiply by 0.01f, bit-identical to the reference.)
//
// R4: drop the shared-memory staging. item_memory is 10 MB -> L2-resident.
// Each output float4 is built from the two aligned float4s that straddle the
// rotated window (B is the neighbor lane's A -> L1 hit). This removes the
// 2x smem crossbar traffic that made L1 the binding pipe (82.8%) and the
// 40 KB smem that capped occupancy at 59%.

#define HDC_D    10000
#define HDC_D4   2500      // D / 4
#define HDC_S    2048
#define NTHREADS 256

__global__ void __launch_bounds__(NTHREADS)
hdc_encode_kernel(const int* __restrict__ tok,
                  const float4* __restrict__ item,   // [V][D4]
                  float4* __restrict__ out)          // [B*S][D4]
{
    const int row = blockIdx.x;          // 0 .. B*S-1
    const int i   = row & (HDC_S - 1);   // position within sequence
    const int t   = __ldg(tok + row);

    const int Dmi = HDC_D - i;           // rotation: out_flat[d] = row_flat[(d + Dmi) % D]
    int r4        = Dmi >> 2;            // rotation in float4 units (2500 when i == 0)
    const int a   = Dmi & 3;             // residual element shift 0..3
    if (r4 >= HDC_D4) r4 -= HDC_D4;

    const float4* __restrict__ src  = item + (size_t)t * HDC_D4;
    float4* __restrict__       orow = out  + (size_t)row * HDC_D4;
    const float sc = 0.01f;

    // out4[q] = floats src_flat[4*(q + r4) + a .. +3]  (mod D)
    // k tracks (q + r4) mod D4 incrementally — no per-iter modulo.
    int q = threadIdx.x;
    int k = q + r4; if (k >= HDC_D4) k -= HDC_D4;

    if (a == 0) {
        for (; q < HDC_D4; q += NTHREADS) {
            float4 A = __ldg(src + k);
            float4 v; v.x = A.x * sc; v.y = A.y * sc; v.z = A.z * sc; v.w = A.w * sc;
            __stcs(orow + q, v);
            k += NTHREADS; if (k >= HDC_D4) k -= HDC_D4;
        }
    } else if (a == 1) {
        for (; q < HDC_D4; q += NTHREADS) {
            int kn = k + 1; if (kn == HDC_D4) kn = 0;
            float4 A = __ldg(src + k);
            float4 B = __ldg(src + kn);
            float4 v; v.x = A.y * sc; v.y = A.z * sc; v.z = A.w * sc; v.w = B.x * sc;
            __stcs(orow + q, v);
            k += NTHREADS; if (k >= HDC_D4) k -= HDC_D4;
        }
    } else if (a == 2) {
        for (; q < HDC_D4; q += NTHREADS) {
            int kn = k + 1; if (kn == HDC_D4) kn = 0;
            float4 A = __ldg(src + k);
            float4 B = __ldg(src + kn);
            float4 v; v.x = A.z * sc; v.y = A.w * sc; v.z = B.x * sc; v.w = B.y * sc;
            __stcs(orow + q, v);
            k += NTHREADS; if (k >= HDC_D4) k -= HDC_D4;
        }
    } else {
        for (; q < HDC_D4; q += NTHREADS) {
            int kn = k + 1; if (kn == HDC_D4) kn = 0;
            float4 A = __ldg(src + k);
            float4 B = __ldg(src + kn);
            float4 v; v.x = A.w * sc; v.y = B.x * sc; v.z = B.y * sc; v.w = B.z * sc;
            __stcs(orow + q, v);
            k += NTHREADS; if (k >= HDC_D4) k -= HDC_D4;
        }
    }
}

extern "C" void kernel_launch(void* const* d_in, const int* in_sizes, int n_in,
                              void* d_out, int out_size)
{
    // Inputs: token_ids (int32, B*S=16384), item_memory (f32, V*D).
    // Robust to ordering: tokens is the smaller buffer.
    const void* p0 = d_in[0];
    const void* p1 = d_in[1];
    const int*    tok;
    const float4* item;
    int n_rows;
    if (in_sizes[0] <= in_sizes[1]) {
        tok    = (const int*)p0;
        item   = (const float4*)p1;
        n_rows = in_sizes[0];
    } else {
        tok    = (const int*)p1;
        item   = (const float4*)p0;
        n_rows = in_sizes[1];
    }

    float4* out = (float4*)d_out;
    hdc_encode_kernel<<<n_rows, NTHREADS>>>(tok, item, out);
}

// round 10
// speedup vs baseline: 1.3946x; 1.0063x over previous
#include <cuda_runtime.h>
#include <stdint.h>

// HDCTokenEncoder: out[b,i,d] = item_memory[tok[b,i]][(d - i) mod D] * 0.01f
// (L2 norm of every +/-1 row of length 10000 is exactly 100, exact in fp32,
//  so normalization == multiply by 0.01f, bit-identical to the reference.)
//
// R6: kill the second (B) global load. Consecutive lanes hold consecutive
// k (mod D4), so the straddle components come from lane+1 via shfl; only
// lane 31 does a tiny predicated load. Cuts L1 wavefronts/128B from ~3 to ~2.

#define HDC_D    10000
#define HDC_D4   2500      // D / 4
#define HDC_S    2048
#define NTHREADS 256
#define NITER    10        // ceil(HDC_D4 / NTHREADS)

__global__ void __launch_bounds__(NTHREADS)
hdc_encode_kernel(const int* __restrict__ tok,
                  const float4* __restrict__ item,   // [V][D4]
                  float4* __restrict__ out)          // [B*S][D4]
{
    const int row = blockIdx.x;          // 0 .. B*S-1
    const int i   = row & (HDC_S - 1);   // position within sequence
    const int t   = __ldg(tok + row);

    const int Dmi = HDC_D - i;           // rotation: out_flat[d] = row_flat[(d + Dmi) % D]
    int r4        = Dmi >> 2;            // rotation in float4 units (2500 when i == 0)
    const int a   = Dmi & 3;             // residual element shift 0..3
    if (r4 >= HDC_D4) r4 -= HDC_D4;

    const float4* __restrict__ src  = item + (size_t)t * HDC_D4;
    const float*  __restrict__ srcf = (const float*)src;
    float4* __restrict__       orow = out  + (size_t)row * HDC_D4;
    const float sc   = 0.01f;
    const int   lane = threadIdx.x & 31;

    // out4[q] = floats src_flat[4*(q + r4) + a .. +3] (mod D).
    // k == (q + r4) mod D4 maintained incrementally. Within a warp consecutive
    // lanes hold consecutive k (mod D4), so B (= src4[(k+1) mod D4]) is the
    // next lane's A — fetched with shfl.down; lane 31 loads it directly.
    int q = threadIdx.x;
    int k = q + r4; if (k >= HDC_D4) k -= HDC_D4;

    if (a == 0) {
        for (; q < HDC_D4; q += NTHREADS) {
            float4 A = __ldg(src + k);
            float4 v; v.x = A.x * sc; v.y = A.y * sc; v.z = A.z * sc; v.w = A.w * sc;
            __stcs(orow + q, v);
            k += NTHREADS; if (k >= HDC_D4) k -= HDC_D4;
        }
        return;
    }

    // a != 0 paths: fixed trip count, all lanes converged for the shuffles.
    // Loads always use wrapped k (in-bounds even when q >= D4); store predicated.
    if (a == 1) {
        #pragma unroll
        for (int it = 0; it < NITER; ++it) {
            float4 A  = __ldg(src + k);
            float  bx = __shfl_down_sync(0xffffffffu, A.x, 1);
            if (lane == 31) {
                int kn = k + 1; if (kn == HDC_D4) kn = 0;
                bx = __ldg(srcf + 4 * kn);
            }
            if (q < HDC_D4) {
                float4 v; v.x = A.y * sc; v.y = A.z * sc; v.z = A.w * sc; v.w = bx * sc;
                __stcs(orow + q, v);
            }
            q += NTHREADS;
            k += NTHREADS; if (k >= HDC_D4) k -= HDC_D4;
        }
    } else if (a == 2) {
        #pragma unroll
        for (int it = 0; it < NITER; ++it) {
            float4 A  = __ldg(src + k);
            float  bx = __shfl_down_sync(0xffffffffu, A.x, 1);
            float  by = __shfl_down_sync(0xffffffffu, A.y, 1);
            if (lane == 31) {
                int kn = k + 1; if (kn == HDC_D4) kn = 0;
                float2 Bv = __ldg((const float2*)(srcf + 4 * kn));  // 16B-aligned
                bx = Bv.x; by = Bv.y;
            }
            if (q < HDC_D4) {
                float4 v; v.x = A.z * sc; v.y = A.w * sc; v.z = bx * sc; v.w = by * sc;
                __stcs(orow + q, v);
            }
            q += NTHREADS;
            k += NTHREADS; if (k >= HDC_D4) k -= HDC_D4;
        }
    } else {  // a == 3
        #pragma unroll
        for (int it = 0; it < NITER; ++it) {
            float4 A  = __ldg(src + k);
            float  bx = __shfl_down_sync(0xffffffffu, A.x, 1);
            float  by = __shfl_down_sync(0xffffffffu, A.y, 1);
            float  bz = __shfl_down_sync(0xffffffffu, A.z, 1);
            if (lane == 31) {
                int kn = k + 1; if (kn == HDC_D4) kn = 0;
                float4 Bv = __ldg(src + kn);
                bx = Bv.x; by = Bv.y; bz = Bv.z;
            }
            if (q < HDC_D4) {
                float4 v; v.x = A.w * sc; v.y = bx * sc; v.z = by * sc; v.w = bz * sc;
                __stcs(orow + q, v);
            }
            q += NTHREADS;
            k += NTHREADS; if (k >= HDC_D4) k -= HDC_D4;
        }
    }
}

extern "C" void kernel_launch(void* const* d_in, const int* in_sizes, int n_in,
                              void* d_out, int out_size)
{
    // Inputs: token_ids (int32, B*S=16384), item_memory (f32, V*D).
    // Robust to ordering: tokens is the smaller buffer.
    const void* p0 = d_in[0];
    const void* p1 = d_in[1];
    const int*    tok;
    const float4* item;
    int n_rows;
    if (in_sizes[0] <= in_sizes[1]) {
        tok    = (const int*)p0;
        item   = (const float4*)p1;
        n_rows = in_sizes[0];
    } else {
        tok    = (const int*)p1;
        item   = (const float4*)p0;
        n_rows = in_sizes[1];
    }

    float4* out = (float4*)d_out;
    hdc_encode_kernel<<<n_rows, NTHREADS>>>(tok, item, out);
}